// round 8
// baseline (speedup 1.0000x reference)
#include <cuda_runtime.h>
#include <cuda_bf16.h>
#include <cstdint>

// ---------------------------------------------------------------------------
// Problem dims
// ---------------------------------------------------------------------------
#define B_DIM 64
#define S_DIM 2048
#define H_DIM 512
#define M_DIM (B_DIM * S_DIM)   // 131072
#define NEG_INF_SCORE (-1e9f)

// GEMM tiling: CTA 128x128, K chunks of 64, 16 warps (4m x 4n), warp 32x32
#define KC 64
#define NKCH (H_DIM / KC)        // 8
#define MT 128
#define NT 128
#define NTILES (H_DIM / NT)      // 4
#define NMTILES (M_DIM / MT)     // 1024
#define NSTAGE 3

// SMEM stage layout (bytes)
#define A_HI 0
#define A_LO 16384
#define B_HI 32768
#define B_LO 49152
#define STAGE 65536
#define GEMM_SMEM (NSTAGE * STAGE)   // 192 KB

// Context s-chunking
#define SCHUNK 32
#define S_PER_CHUNK (S_DIM / SCHUNK)  // 64

// ---------------------------------------------------------------------------
// Device scratch (static only). W bf16 hi/lo pre-swizzled tiles: tile (nt,c)
// is 128 n-rows x 64 k, 16 KB, SW128-swizzled 128B rows.
// ---------------------------------------------------------------------------
__device__ __align__(16) __nv_bfloat16 g_Whi[H_DIM * H_DIM];
__device__ __align__(16) __nv_bfloat16 g_Wlo[H_DIM * H_DIM];
__device__ float g_score_part[NTILES * M_DIM];
__device__ float g_ctx_part[SCHUNK * B_DIM * H_DIM];

__device__ __forceinline__ uint32_t smem_u32(const void* p) {
    uint32_t a;
    asm("{ .reg .u64 t; cvta.to.shared.u64 t, %1; cvt.u32.u64 %0, t; }" : "=r"(a) : "l"(p));
    return a;
}
// SW128 swizzle of (row-byte-base, column-byte-offset<128). Exact and in-bounds.
__device__ __forceinline__ uint32_t swz(uint32_t rowoff, uint32_t col) {
    return rowoff + (col ^ ((rowoff >> 3) & 0x70));
}

__device__ __forceinline__ void cp_async16(uint32_t dst, const void* src) {
    asm volatile("cp.async.cg.shared.global [%0], [%1], 16;"
                 :: "r"(dst), "l"(__cvta_generic_to_global(src)) : "memory");
}
__device__ __forceinline__ void cp_async_commit() {
    asm volatile("cp.async.commit_group;" ::: "memory");
}
__device__ __forceinline__ void cp_async_wait0() {
    asm volatile("cp.async.wait_group 0;" ::: "memory");
}

__device__ __forceinline__ void ldsm_x4(uint32_t* r, uint32_t addr) {
    asm volatile("ldmatrix.sync.aligned.m8n8.x4.shared.b16 {%0,%1,%2,%3}, [%4];"
                 : "=r"(r[0]), "=r"(r[1]), "=r"(r[2]), "=r"(r[3]) : "r"(addr));
}

__device__ __forceinline__ void mma16816(float* d, const uint32_t* a, uint32_t b0, uint32_t b1) {
    asm volatile(
        "mma.sync.aligned.m16n8k16.row.col.f32.bf16.bf16.f32 "
        "{%0,%1,%2,%3}, {%4,%5,%6,%7}, {%8,%9}, {%0,%1,%2,%3};"
        : "+f"(d[0]), "+f"(d[1]), "+f"(d[2]), "+f"(d[3])
        : "r"(a[0]), "r"(a[1]), "r"(a[2]), "r"(a[3]), "r"(b0), "r"(b1));
}

// pack 4 floats -> hi uint2 + lo uint2 (bf16 pairs)
__device__ __forceinline__ void split4(float4 xv, uint2* hi, uint2* lo) {
    __nv_bfloat16 h0 = __float2bfloat16(xv.x);
    __nv_bfloat16 h1 = __float2bfloat16(xv.y);
    __nv_bfloat16 h2 = __float2bfloat16(xv.z);
    __nv_bfloat16 h3 = __float2bfloat16(xv.w);
    __nv_bfloat16 l0 = __float2bfloat16(xv.x - __bfloat162float(h0));
    __nv_bfloat16 l1 = __float2bfloat16(xv.y - __bfloat162float(h1));
    __nv_bfloat16 l2 = __float2bfloat16(xv.z - __bfloat162float(h2));
    __nv_bfloat16 l3 = __float2bfloat16(xv.w - __bfloat162float(h3));
    union { __nv_bfloat162 b2[2]; uint2 u; } ph, pl;
    ph.b2[0] = __halves2bfloat162(h0, h1); ph.b2[1] = __halves2bfloat162(h2, h3);
    pl.b2[0] = __halves2bfloat162(l0, l1); pl.b2[1] = __halves2bfloat162(l2, l3);
    *hi = ph.u; *lo = pl.u;
}

// ---------------------------------------------------------------------------
// W pre-convert: fp32 [512(n),512(k)] -> pre-swizzled bf16 hi/lo tiles
// grid: 32 blocks (nt*8+c), 256 threads
// ---------------------------------------------------------------------------
__global__ void __launch_bounds__(256)
convert_w_kernel(const float* __restrict__ W)
{
    const int nt = blockIdx.x >> 3;
    const int c  = blockIdx.x & 7;
    const int tid = threadIdx.x;
    const int row = tid >> 1;              // 0..127 (n within tile)
    const int kh  = (tid & 1) * 32;        // k element offset half-row

    const float* src = W + (size_t)(nt * NT + row) * H_DIM + c * KC + kh;
    char* dhi = (char*)g_Whi + (size_t)(blockIdx.x) * 16384;
    char* dlo = (char*)g_Wlo + (size_t)(blockIdx.x) * 16384;

    const uint32_t rowoff = (uint32_t)row * 128;
    #pragma unroll
    for (int i = 0; i < 8; i++) {
        float4 xv = *(const float4*)(src + i * 4);
        uint2 hi, lo;
        split4(xv, &hi, &lo);
        const uint32_t off = swz(rowoff, (uint32_t)(kh * 2 + i * 8));
        *(uint2*)(dhi + off) = hi;
        *(uint2*)(dlo + off) = lo;
    }
}

// ---------------------------------------------------------------------------
// Scores GEMM via mma.sync (bf16 hi/lo split, fp32 accum), fused tanh.v reduce
// grid (1024 m-tiles, 4 n-tiles), 512 threads / 16 warps (4m x 4n)
// 3-stage pipeline.
// ---------------------------------------------------------------------------
__global__ void __launch_bounds__(512, 1)
scores_gemm_mma(const float* __restrict__ X,
                const float* __restrict__ bias,
                const float* __restrict__ v)
{
    extern __shared__ char smem[];
    __shared__ float red[4][MT];

    const uint32_t sb = smem_u32(smem);
    const int tid  = threadIdx.x;
    const int wid  = tid >> 5;
    const int lane = tid & 31;
    const int wm   = wid & 3;      // warp m index (0..3)
    const int wn   = wid >> 2;     // warp n index (0..3)
    const int t  = blockIdx.x;     // m-tile
    const int nt = blockIdx.y;     // n-tile

    // A global mapping: thread owns row = tid>>2, k-quarter = (tid&3)*16 elems
    const int arow = tid >> 2;                // 0..127
    const int akq  = (tid & 3) * 16;          // k element offset (16 elems)
    const float* aptr = X + (size_t)(t * MT + arow) * H_DIM + akq;
    const uint32_t a_rowoff = (uint32_t)arow * 128;
    const uint32_t a_colbase = (uint32_t)(akq * 2);   // 0,32,64,96 bytes

    // B global tiles (pre-swizzled 16KB blobs)
    const char* bhig = (const char*)g_Whi + (size_t)(nt * NKCH) * 16384;
    const char* blog = (const char*)g_Wlo + (size_t)(nt * NKCH) * 16384;

    // ldmatrix row bases; column = kb + ks*32 composed inside the swizzle
    const int lrow = lane & 15;
    const uint32_t kb = (lane >> 4) * 16;
    uint32_t a_rowb[2], b_rowb[2];
    #pragma unroll
    for (int mi = 0; mi < 2; mi++)
        a_rowb[mi] = (uint32_t)(wm * 32 + mi * 16 + lrow) * 128;
    #pragma unroll
    for (int np = 0; np < 2; np++)
        b_rowb[np] = (uint32_t)(wn * 32 + np * 16 + lrow) * 128;

    float acc[2][4][4];
    #pragma unroll
    for (int mi = 0; mi < 2; mi++)
        #pragma unroll
        for (int ni = 0; ni < 4; ni++)
            #pragma unroll
            for (int j = 0; j < 4; j++) acc[mi][ni][j] = 0.f;

    // helper lambdas ------------------------------------------------------
    auto b_load = [&](int c) {   // cp.async B hi+lo for chunk c into stage c%3
        const uint32_t stb = sb + (uint32_t)(c % NSTAGE) * STAGE;
        const char* bh = bhig + (size_t)c * 16384;
        const char* bl = blog + (size_t)c * 16384;
        #pragma unroll
        for (int it = 0; it < 2; it++) {
            cp_async16(stb + B_HI + tid * 16 + it * 8192, bh + tid * 16 + it * 8192);
            cp_async16(stb + B_LO + tid * 16 + it * 8192, bl + tid * 16 + it * 8192);
        }
        cp_async_commit();
    };
    auto a_ldg = [&](int c, float4* areg) {
        #pragma unroll
        for (int i = 0; i < 4; i++)
            areg[i] = *(const float4*)(aptr + c * KC + i * 4);
    };
    auto a_sts = [&](int c, const float4* areg) {
        char* st = smem + (size_t)(c % NSTAGE) * STAGE;
        #pragma unroll
        for (int i = 0; i < 4; i++) {
            uint2 hi, lo;
            split4(areg[i], &hi, &lo);
            const uint32_t off = swz(a_rowoff, a_colbase + i * 8);
            *(uint2*)(st + A_HI + off) = hi;
            *(uint2*)(st + A_LO + off) = lo;
        }
    };

    // ---- prologue: chunks 0 and 1 ----
    {
        b_load(0);
        b_load(1);
        float4 ar0[4], ar1[4];
        a_ldg(0, ar0);
        a_ldg(1, ar1);
        a_sts(0, ar0);
        a_sts(1, ar1);
    }
    __syncthreads();

    for (int c = 0; c < NKCH; c++) {
        // B(c) was committed 2 iterations back; one newer group may be pending
        if (c == NKCH - 1) cp_async_wait0();
        else asm volatile("cp.async.wait_group 1;" ::: "memory");
        __syncthreads();

        float4 areg[4];
        if (c + 2 < NKCH) {
            b_load(c + 2);          // async, overlaps compute below
            a_ldg(c + 2, areg);     // latency hidden by compute
        }

        // ---- compute chunk c ----
        const uint32_t st = sb + (uint32_t)(c % NSTAGE) * STAGE;
        #pragma unroll
        for (int ks = 0; ks < KC / 16; ks++) {
            const uint32_t kcol = kb + ks * 32;    // < 128, composed into swizzle
            uint32_t ahi[2][4], alo[2][4], bhi[2][4], blo[2][4];
            #pragma unroll
            for (int mi = 0; mi < 2; mi++) {
                const uint32_t ao = swz(a_rowb[mi], kcol);
                ldsm_x4(ahi[mi], st + A_HI + ao);
                ldsm_x4(alo[mi], st + A_LO + ao);
            }
            #pragma unroll
            for (int np = 0; np < 2; np++) {
                const uint32_t bo = swz(b_rowb[np], kcol);
                ldsm_x4(bhi[np], st + B_HI + bo);
                ldsm_x4(blo[np], st + B_LO + bo);
            }
            #pragma unroll
            for (int mi = 0; mi < 2; mi++)
                #pragma unroll
                for (int np = 0; np < 2; np++)
                    #pragma unroll
                    for (int hf = 0; hf < 2; hf++) {
                        float* d = acc[mi][np * 2 + hf];
                        mma16816(d, ahi[mi], bhi[np][hf], bhi[np][hf + 2]);
                        mma16816(d, ahi[mi], blo[np][hf], blo[np][hf + 2]);
                        mma16816(d, alo[mi], bhi[np][hf], bhi[np][hf + 2]);
                    }
        }

        if (c + 2 < NKCH)
            a_sts(c + 2, areg);     // stage (c+2)%3 is free (consumed at c-1)
    }

    // ---- epilogue: rsum[row] = sum_n v[n]*tanh(acc + b[n]) ----
    const int ncol0 = nt * NT + wn * 32 + (lane & 3) * 2;
    float rs[2][2] = {{0.f, 0.f}, {0.f, 0.f}};
    #pragma unroll
    for (int np = 0; np < 2; np++) {
        #pragma unroll
        for (int hf = 0; hf < 2; hf++) {
            #pragma unroll
            for (int cc = 0; cc < 2; cc++) {
                const int col = ncol0 + np * 16 + hf * 8 + cc;
                const float bb = bias[col];
                const float vv = v[col];
                #pragma unroll
                for (int mi = 0; mi < 2; mi++) {
                    float x0 = acc[mi][np * 2 + hf][cc] + bb;       // row groupID
                    float x1 = acc[mi][np * 2 + hf][cc + 2] + bb;   // row groupID+8
                    float t0, t1;
                    asm("tanh.approx.f32 %0, %1;" : "=f"(t0) : "f"(x0));
                    asm("tanh.approx.f32 %0, %1;" : "=f"(t1) : "f"(x1));
                    rs[mi][0] = fmaf(t0, vv, rs[mi][0]);
                    rs[mi][1] = fmaf(t1, vv, rs[mi][1]);
                }
            }
        }
    }
    // reduce across the 4 lanes sharing a row (lane bits 0-1)
    #pragma unroll
    for (int mi = 0; mi < 2; mi++)
        #pragma unroll
        for (int h = 0; h < 2; h++) {
            rs[mi][h] += __shfl_xor_sync(0xffffffffu, rs[mi][h], 1);
            rs[mi][h] += __shfl_xor_sync(0xffffffffu, rs[mi][h], 2);
        }

    __syncthreads();   // all compute done before red[] use
    if ((lane & 3) == 0) {
        #pragma unroll
        for (int mi = 0; mi < 2; mi++)
            #pragma unroll
            for (int h = 0; h < 2; h++)
                red[wn][wm * 32 + mi * 16 + h * 8 + (lane >> 2)] = rs[mi][h];
    }
    __syncthreads();
    if (tid < MT) {
        float s = red[0][tid] + red[1][tid] + red[2][tid] + red[3][tid];
        g_score_part[(size_t)nt * M_DIM + (size_t)t * MT + tid] = s;
    }
}

// ---------------------------------------------------------------------------
// Softmax (folds 4 n-tile partials), mask as int32
// ---------------------------------------------------------------------------
__device__ __forceinline__ float warp_max(float v) {
    #pragma unroll
    for (int o = 16; o > 0; o >>= 1) v = fmaxf(v, __shfl_xor_sync(0xffffffffu, v, o));
    return v;
}
__device__ __forceinline__ float warp_sum(float v) {
    #pragma unroll
    for (int o = 16; o > 0; o >>= 1) v += __shfl_xor_sync(0xffffffffu, v, o);
    return v;
}

__global__ void __launch_bounds__(256)
softmax_kernel(const int* __restrict__ mask, float* __restrict__ weights)
{
    const int b    = blockIdx.x;
    const int tid  = threadIdx.x;
    const int lane = tid & 31;
    const int wid  = tid >> 5;

    __shared__ float red[8];

    float vals[8];
    float mx = -3.4e38f;
    #pragma unroll
    for (int i = 0; i < 8; i++) {
        const size_t m = (size_t)b * S_DIM + tid + i * 256;
        float sc = 0.f;
        #pragma unroll
        for (int n = 0; n < NTILES; n++)
            sc += g_score_part[(size_t)n * M_DIM + m];
        if (mask[m] == 0) sc = NEG_INF_SCORE;
        vals[i] = sc;
        mx = fmaxf(mx, sc);
    }

    mx = warp_max(mx);
    if (lane == 0) red[wid] = mx;
    __syncthreads();
    float bmax = red[0];
    #pragma unroll
    for (int i = 1; i < 8; i++) bmax = fmaxf(bmax, red[i]);
    __syncthreads();

    float s_sum = 0.f;
    #pragma unroll
    for (int i = 0; i < 8; i++) {
        vals[i] = __expf(vals[i] - bmax);
        s_sum += vals[i];
    }
    s_sum = warp_sum(s_sum);
    if (lane == 0) red[wid] = s_sum;
    __syncthreads();
    float total = red[0];
    #pragma unroll
    for (int i = 1; i < 8; i++) total += red[i];

    const float inv = 1.0f / total;
    #pragma unroll
    for (int i = 0; i < 8; i++)
        weights[(size_t)b * S_DIM + tid + i * 256] = vals[i] * inv;
}

// ---------------------------------------------------------------------------
// Context: weighted sum over S (memory-bound second pass over hidden)
// ---------------------------------------------------------------------------
__global__ void __launch_bounds__(128)
context_part_kernel(const float* __restrict__ hidden, const float* __restrict__ weights)
{
    const int sc = blockIdx.x;          // 0..31
    const int b  = blockIdx.y;          // 0..63
    const int h4 = threadIdx.x * 4;

    const int s0 = sc * S_PER_CHUNK;
    const float* wrow  = weights + (size_t)b * S_DIM + s0;
    const float* hbase = hidden + ((size_t)b * S_DIM + s0) * H_DIM + h4;

    float4 acc = make_float4(0.f, 0.f, 0.f, 0.f);
    #pragma unroll 8
    for (int s = 0; s < S_PER_CHUNK; s++) {
        const float w = wrow[s];
        float4 hv = *(const float4*)(hbase + (size_t)s * H_DIM);
        acc.x = fmaf(w, hv.x, acc.x);
        acc.y = fmaf(w, hv.y, acc.y);
        acc.z = fmaf(w, hv.z, acc.z);
        acc.w = fmaf(w, hv.w, acc.w);
    }
    *(float4*)(g_ctx_part + ((size_t)(sc * B_DIM + b)) * H_DIM + h4) = acc;
}

__global__ void __launch_bounds__(256)
context_reduce_kernel(float* __restrict__ context)
{
    const int i = blockIdx.x * blockDim.x + threadIdx.x;
    float s = 0.f;
    #pragma unroll
    for (int n = 0; n < SCHUNK; n++)
        s += g_ctx_part[(size_t)n * (B_DIM * H_DIM) + i];
    context[i] = s;
}

// ---------------------------------------------------------------------------
extern "C" void kernel_launch(void* const* d_in, const int* in_sizes, int n_in,
                              void* d_out, int out_size)
{
    (void)in_sizes; (void)n_in; (void)out_size;
    const float* hidden = (const float*)d_in[0];
    const int*   mask   = (const int*)d_in[1];
    const float* W      = (const float*)d_in[2];
    const float* bias   = (const float*)d_in[3];
    const float* v      = (const float*)d_in[4];

    float* context = (float*)d_out;                          // [B, H]
    float* weights = (float*)d_out + (size_t)B_DIM * H_DIM;  // [B, S]

    cudaFuncSetAttribute(scores_gemm_mma,
                         cudaFuncAttributeMaxDynamicSharedMemorySize, GEMM_SMEM);

    convert_w_kernel<<<NTILES * NKCH, 256>>>(W);

    scores_gemm_mma<<<dim3(NMTILES, NTILES), 512, GEMM_SMEM>>>(hidden, bias, v);

    softmax_kernel<<<B_DIM, 256>>>(mask, weights);

    context_part_kernel<<<dim3(SCHUNK, B_DIM), 128>>>(hidden, weights);
    context_reduce_kernel<<<(B_DIM * H_DIM) / 256, 256>>>(context);
}

// round 9
// speedup vs baseline: 1.2912x; 1.2912x over previous
#include <cuda_runtime.h>
#include <cuda_bf16.h>
#include <cuda_fp16.h>
#include <cstdint>

// ---------------------------------------------------------------------------
// Problem dims
// ---------------------------------------------------------------------------
#define B_DIM 64
#define S_DIM 2048
#define H_DIM 512
#define M_DIM (B_DIM * S_DIM)   // 131072
#define NEG_INF_SCORE (-1e9f)

// GEMM tiling: CTA 128x128, K chunks of 64, 16 warps (4m x 4n), warp 32x32
#define KC 64
#define NKCH (H_DIM / KC)        // 8
#define MT 128
#define NT 128
#define NTILES (H_DIM / NT)      // 4
#define NMTILES (M_DIM / MT)     // 1024
#define NSTAGE 4

// SMEM stage layout (bytes): A fp16 16KB, B hi 16KB, B lo 16KB
#define A_HI 0
#define B_HI 16384
#define B_LO 32768
#define STAGE 49152
#define GEMM_SMEM (NSTAGE * STAGE)   // 192 KB

// Context s-chunking
#define SCHUNK 32
#define S_PER_CHUNK (S_DIM / SCHUNK)  // 64

// ---------------------------------------------------------------------------
// Device scratch (static only). W fp16 hi/lo pre-swizzled tiles: tile (nt,c)
// is 128 n-rows x 64 k, 16 KB, SW128-swizzled 128B rows.
// ---------------------------------------------------------------------------
__device__ __align__(16) __half g_Whi[H_DIM * H_DIM];
__device__ __align__(16) __half g_Wlo[H_DIM * H_DIM];
__device__ float g_score_part[NTILES * M_DIM];
__device__ float g_ctx_part[SCHUNK * B_DIM * H_DIM];

__device__ __forceinline__ uint32_t smem_u32(const void* p) {
    uint32_t a;
    asm("{ .reg .u64 t; cvta.to.shared.u64 t, %1; cvt.u32.u64 %0, t; }" : "=r"(a) : "l"(p));
    return a;
}
// SW128 swizzle of (row-byte-base, column-byte-offset<128). Exact and in-bounds.
__device__ __forceinline__ uint32_t swz(uint32_t rowoff, uint32_t col) {
    return rowoff + (col ^ ((rowoff >> 3) & 0x70));
}

__device__ __forceinline__ void cp_async16(uint32_t dst, const void* src) {
    asm volatile("cp.async.cg.shared.global [%0], [%1], 16;"
                 :: "r"(dst), "l"(__cvta_generic_to_global(src)) : "memory");
}
__device__ __forceinline__ void cp_async_commit() {
    asm volatile("cp.async.commit_group;" ::: "memory");
}

__device__ __forceinline__ void ldsm_x4(uint32_t* r, uint32_t addr) {
    asm volatile("ldmatrix.sync.aligned.m8n8.x4.shared.b16 {%0,%1,%2,%3}, [%4];"
                 : "=r"(r[0]), "=r"(r[1]), "=r"(r[2]), "=r"(r[3]) : "r"(addr));
}

__device__ __forceinline__ void mma16816(float* d, const uint32_t* a, uint32_t b0, uint32_t b1) {
    asm volatile(
        "mma.sync.aligned.m16n8k16.row.col.f32.f16.f16.f32 "
        "{%0,%1,%2,%3}, {%4,%5,%6,%7}, {%8,%9}, {%0,%1,%2,%3};"
        : "+f"(d[0]), "+f"(d[1]), "+f"(d[2]), "+f"(d[3])
        : "r"(a[0]), "r"(a[1]), "r"(a[2]), "r"(a[3]), "r"(b0), "r"(b1));
}

// pack 2 floats -> one fp16x2 register
__device__ __forceinline__ uint32_t pack_h2(float x, float y) {
    __half2 h = __floats2half2_rn(x, y);
    return *reinterpret_cast<uint32_t*>(&h);
}

// ---------------------------------------------------------------------------
// W pre-convert: fp32 [512(n),512(k)] -> pre-swizzled fp16 hi/lo tiles
// grid: 32 blocks (nt*8+c), 256 threads
// ---------------------------------------------------------------------------
__global__ void __launch_bounds__(256)
convert_w_kernel(const float* __restrict__ W)
{
    const int nt = blockIdx.x >> 3;
    const int c  = blockIdx.x & 7;
    const int tid = threadIdx.x;
    const int row = tid >> 1;              // 0..127 (n within tile)
    const int kh  = (tid & 1) * 32;        // k element offset half-row

    const float* src = W + (size_t)(nt * NT + row) * H_DIM + c * KC + kh;
    char* dhi = (char*)g_Whi + (size_t)(blockIdx.x) * 16384;
    char* dlo = (char*)g_Wlo + (size_t)(blockIdx.x) * 16384;

    const uint32_t rowoff = (uint32_t)row * 128;
    #pragma unroll
    for (int i = 0; i < 8; i++) {
        float4 xv = *(const float4*)(src + i * 4);
        __half h0 = __float2half_rn(xv.x);
        __half h1 = __float2half_rn(xv.y);
        __half h2 = __float2half_rn(xv.z);
        __half h3 = __float2half_rn(xv.w);
        uint2 hi, lo;
        hi.x = pack_h2(xv.x, xv.y);   // == packed h0,h1
        hi.y = pack_h2(xv.z, xv.w);
        lo.x = pack_h2(xv.x - __half2float(h0), xv.y - __half2float(h1));
        lo.y = pack_h2(xv.z - __half2float(h2), xv.w - __half2float(h3));
        const uint32_t off = swz(rowoff, (uint32_t)(kh * 2 + i * 8));
        *(uint2*)(dhi + off) = hi;
        *(uint2*)(dlo + off) = lo;
    }
}

// ---------------------------------------------------------------------------
// Scores GEMM via mma.sync fp16 (W hi/lo split, X single fp16, fp32 accum),
// fused tanh.v reduce. grid (1024, 4), 512 threads / 16 warps, 4-stage pipe.
// ---------------------------------------------------------------------------
__global__ void __launch_bounds__(512, 1)
scores_gemm_mma(const float* __restrict__ X,
                const float* __restrict__ bias,
                const float* __restrict__ v)
{
    extern __shared__ char smem[];
    __shared__ float red[4][MT];

    const uint32_t sb = smem_u32(smem);
    const int tid  = threadIdx.x;
    const int wid  = tid >> 5;
    const int lane = tid & 31;
    const int wm   = wid & 3;      // warp m index (0..3)
    const int wn   = wid >> 2;     // warp n index (0..3)
    const int t  = blockIdx.x;     // m-tile
    const int nt = blockIdx.y;     // n-tile

    // A global mapping: thread owns row = tid>>2, k-quarter = (tid&3)*16 elems
    const int arow = tid >> 2;                // 0..127
    const int akq  = (tid & 3) * 16;          // k element offset (16 elems)
    const float* aptr = X + (size_t)(t * MT + arow) * H_DIM + akq;
    const uint32_t a_rowoff = (uint32_t)arow * 128;
    const uint32_t a_colbase = (uint32_t)(akq * 2);   // 0,32,64,96 bytes (fp16)

    // B global tiles (pre-swizzled 16KB blobs)
    const char* bhig = (const char*)g_Whi + (size_t)(nt * NKCH) * 16384;
    const char* blog = (const char*)g_Wlo + (size_t)(nt * NKCH) * 16384;

    // ldmatrix row bases; column = kb + ks*32 composed inside the swizzle
    const int lrow = lane & 15;
    const uint32_t kb = (lane >> 4) * 16;
    uint32_t a_rowb[2], b_rowb[2];
    #pragma unroll
    for (int mi = 0; mi < 2; mi++)
        a_rowb[mi] = (uint32_t)(wm * 32 + mi * 16 + lrow) * 128;
    #pragma unroll
    for (int np = 0; np < 2; np++)
        b_rowb[np] = (uint32_t)(wn * 32 + np * 16 + lrow) * 128;

    float acc[2][4][4];
    #pragma unroll
    for (int mi = 0; mi < 2; mi++)
        #pragma unroll
        for (int ni = 0; ni < 4; ni++)
            #pragma unroll
            for (int j = 0; j < 4; j++) acc[mi][ni][j] = 0.f;

    // helper lambdas ------------------------------------------------------
    auto b_load = [&](int c) {   // cp.async B hi+lo for chunk c into stage c%4
        const uint32_t stb = sb + (uint32_t)(c % NSTAGE) * STAGE;
        const char* bh = bhig + (size_t)c * 16384;
        const char* bl = blog + (size_t)c * 16384;
        #pragma unroll
        for (int it = 0; it < 2; it++) {
            cp_async16(stb + B_HI + tid * 16 + it * 8192, bh + tid * 16 + it * 8192);
            cp_async16(stb + B_LO + tid * 16 + it * 8192, bl + tid * 16 + it * 8192);
        }
        cp_async_commit();
    };
    auto a_ldg = [&](int c, float4* areg) {
        #pragma unroll
        for (int i = 0; i < 4; i++)
            areg[i] = *(const float4*)(aptr + c * KC + i * 4);
    };
    auto a_sts = [&](int c, const float4* areg) {   // fp16 single-rounded
        char* st = smem + (size_t)(c % NSTAGE) * STAGE;
        uint4 v0, v1;
        v0.x = pack_h2(areg[0].x, areg[0].y);
        v0.y = pack_h2(areg[0].z, areg[0].w);
        v0.z = pack_h2(areg[1].x, areg[1].y);
        v0.w = pack_h2(areg[1].z, areg[1].w);
        v1.x = pack_h2(areg[2].x, areg[2].y);
        v1.y = pack_h2(areg[2].z, areg[2].w);
        v1.z = pack_h2(areg[3].x, areg[3].y);
        v1.w = pack_h2(areg[3].z, areg[3].w);
        *(uint4*)(st + A_HI + swz(a_rowoff, a_colbase))      = v0;
        *(uint4*)(st + A_HI + swz(a_rowoff, a_colbase + 16)) = v1;
    };

    // ---- prologue: chunks 0, 1, 2 ----
    {
        b_load(0); b_load(1); b_load(2);
        float4 ar[4];
        a_ldg(0, ar); a_sts(0, ar);
        a_ldg(1, ar); a_sts(1, ar);
        a_ldg(2, ar); a_sts(2, ar);
    }
    __syncthreads();

    for (int c = 0; c < NKCH; c++) {
        if (c < NKCH - 2)      asm volatile("cp.async.wait_group 2;" ::: "memory");
        else if (c == NKCH - 2) asm volatile("cp.async.wait_group 1;" ::: "memory");
        else                    asm volatile("cp.async.wait_group 0;" ::: "memory");
        __syncthreads();

        float4 areg[4];
        if (c + 3 < NKCH) {
            b_load(c + 3);          // async, overlaps compute below
            a_ldg(c + 3, areg);     // latency hidden by compute
        }

        // ---- compute chunk c, fragment ping-pong over ks ----
        const uint32_t st = sb + (uint32_t)(c % NSTAGE) * STAGE;
        uint32_t ah[2][2][4], bh[2][2][4], bl[2][2][4];

        // load ks=0 fragments into buffer 0
        {
            const uint32_t kcol = kb;
            #pragma unroll
            for (int mi = 0; mi < 2; mi++)
                ldsm_x4(ah[0][mi], st + A_HI + swz(a_rowb[mi], kcol));
            #pragma unroll
            for (int np = 0; np < 2; np++) {
                const uint32_t bo = swz(b_rowb[np], kcol);
                ldsm_x4(bh[0][np], st + B_HI + bo);
                ldsm_x4(bl[0][np], st + B_LO + bo);
            }
        }

        #pragma unroll
        for (int ks = 0; ks < KC / 16; ks++) {
            const int cur = ks & 1;
            const int nxt = cur ^ 1;
            if (ks + 1 < KC / 16) {
                const uint32_t kcol = kb + (ks + 1) * 32;
                #pragma unroll
                for (int mi = 0; mi < 2; mi++)
                    ldsm_x4(ah[nxt][mi], st + A_HI + swz(a_rowb[mi], kcol));
                #pragma unroll
                for (int np = 0; np < 2; np++) {
                    const uint32_t bo = swz(b_rowb[np], kcol);
                    ldsm_x4(bh[nxt][np], st + B_HI + bo);
                    ldsm_x4(bl[nxt][np], st + B_LO + bo);
                }
            }
            #pragma unroll
            for (int mi = 0; mi < 2; mi++)
                #pragma unroll
                for (int np = 0; np < 2; np++)
                    #pragma unroll
                    for (int hf = 0; hf < 2; hf++) {
                        float* d = acc[mi][np * 2 + hf];
                        mma16816(d, ah[cur][mi], bh[cur][np][hf], bh[cur][np][hf + 2]);
                        mma16816(d, ah[cur][mi], bl[cur][np][hf], bl[cur][np][hf + 2]);
                    }
        }

        if (c + 3 < NKCH)
            a_sts(c + 3, areg);     // stage (c+3)%4 free (consumed at c-1)
    }

    // ---- epilogue: rsum[row] = sum_n v[n]*tanh(acc + b[n]) ----
    const int ncol0 = nt * NT + wn * 32 + (lane & 3) * 2;
    float rs[2][2] = {{0.f, 0.f}, {0.f, 0.f}};
    #pragma unroll
    for (int np = 0; np < 2; np++) {
        #pragma unroll
        for (int hf = 0; hf < 2; hf++) {
            #pragma unroll
            for (int cc = 0; cc < 2; cc++) {
                const int col = ncol0 + np * 16 + hf * 8 + cc;
                const float bb = bias[col];
                const float vv = v[col];
                #pragma unroll
                for (int mi = 0; mi < 2; mi++) {
                    float x0 = acc[mi][np * 2 + hf][cc] + bb;       // row groupID
                    float x1 = acc[mi][np * 2 + hf][cc + 2] + bb;   // row groupID+8
                    float t0, t1;
                    asm("tanh.approx.f32 %0, %1;" : "=f"(t0) : "f"(x0));
                    asm("tanh.approx.f32 %0, %1;" : "=f"(t1) : "f"(x1));
                    rs[mi][0] = fmaf(t0, vv, rs[mi][0]);
                    rs[mi][1] = fmaf(t1, vv, rs[mi][1]);
                }
            }
        }
    }
    // reduce across the 4 lanes sharing a row (lane bits 0-1)
    #pragma unroll
    for (int mi = 0; mi < 2; mi++)
        #pragma unroll
        for (int h = 0; h < 2; h++) {
            rs[mi][h] += __shfl_xor_sync(0xffffffffu, rs[mi][h], 1);
            rs[mi][h] += __shfl_xor_sync(0xffffffffu, rs[mi][h], 2);
        }

    __syncthreads();   // all compute done before red[] use
    if ((lane & 3) == 0) {
        #pragma unroll
        for (int mi = 0; mi < 2; mi++)
            #pragma unroll
            for (int h = 0; h < 2; h++)
                red[wn][wm * 32 + mi * 16 + h * 8 + (lane >> 2)] = rs[mi][h];
    }
    __syncthreads();
    if (tid < MT) {
        float s = red[0][tid] + red[1][tid] + red[2][tid] + red[3][tid];
        g_score_part[(size_t)nt * M_DIM + (size_t)t * MT + tid] = s;
    }
}

// ---------------------------------------------------------------------------
// Softmax (folds 4 n-tile partials), mask as int32
// ---------------------------------------------------------------------------
__device__ __forceinline__ float warp_max(float v) {
    #pragma unroll
    for (int o = 16; o > 0; o >>= 1) v = fmaxf(v, __shfl_xor_sync(0xffffffffu, v, o));
    return v;
}
__device__ __forceinline__ float warp_sum(float v) {
    #pragma unroll
    for (int o = 16; o > 0; o >>= 1) v += __shfl_xor_sync(0xffffffffu, v, o);
    return v;
}

__global__ void __launch_bounds__(256)
softmax_kernel(const int* __restrict__ mask, float* __restrict__ weights)
{
    const int b    = blockIdx.x;
    const int tid  = threadIdx.x;
    const int lane = tid & 31;
    const int wid  = tid >> 5;

    __shared__ float red[8];

    float vals[8];
    float mx = -3.4e38f;
    #pragma unroll
    for (int i = 0; i < 8; i++) {
        const size_t m = (size_t)b * S_DIM + tid + i * 256;
        float sc = 0.f;
        #pragma unroll
        for (int n = 0; n < NTILES; n++)
            sc += g_score_part[(size_t)n * M_DIM + m];
        if (mask[m] == 0) sc = NEG_INF_SCORE;
        vals[i] = sc;
        mx = fmaxf(mx, sc);
    }

    mx = warp_max(mx);
    if (lane == 0) red[wid] = mx;
    __syncthreads();
    float bmax = red[0];
    #pragma unroll
    for (int i = 1; i < 8; i++) bmax = fmaxf(bmax, red[i]);
    __syncthreads();

    float s_sum = 0.f;
    #pragma unroll
    for (int i = 0; i < 8; i++) {
        vals[i] = __expf(vals[i] - bmax);
        s_sum += vals[i];
    }
    s_sum = warp_sum(s_sum);
    if (lane == 0) red[wid] = s_sum;
    __syncthreads();
    float total = red[0];
    #pragma unroll
    for (int i = 1; i < 8; i++) total += red[i];

    const float inv = 1.0f / total;
    #pragma unroll
    for (int i = 0; i < 8; i++)
        weights[(size_t)b * S_DIM + tid + i * 256] = vals[i] * inv;
}

// ---------------------------------------------------------------------------
// Context: weighted sum over S (memory-bound second pass over hidden)
// ---------------------------------------------------------------------------
__global__ void __launch_bounds__(128)
context_part_kernel(const float* __restrict__ hidden, const float* __restrict__ weights)
{
    const int sc = blockIdx.x;          // 0..31
    const int b  = blockIdx.y;          // 0..63
    const int h4 = threadIdx.x * 4;

    const int s0 = sc * S_PER_CHUNK;
    const float* wrow  = weights + (size_t)b * S_DIM + s0;
    const float* hbase = hidden + ((size_t)b * S_DIM + s0) * H_DIM + h4;

    float4 acc = make_float4(0.f, 0.f, 0.f, 0.f);
    #pragma unroll 8
    for (int s = 0; s < S_PER_CHUNK; s++) {
        const float w = wrow[s];
        float4 hv = *(const float4*)(hbase + (size_t)s * H_DIM);
        acc.x = fmaf(w, hv.x, acc.x);
        acc.y = fmaf(w, hv.y, acc.y);
        acc.z = fmaf(w, hv.z, acc.z);
        acc.w = fmaf(w, hv.w, acc.w);
    }
    *(float4*)(g_ctx_part + ((size_t)(sc * B_DIM + b)) * H_DIM + h4) = acc;
}

__global__ void __launch_bounds__(256)
context_reduce_kernel(float* __restrict__ context)
{
    const int i = blockIdx.x * blockDim.x + threadIdx.x;
    float s = 0.f;
    #pragma unroll
    for (int n = 0; n < SCHUNK; n++)
        s += g_ctx_part[(size_t)n * (B_DIM * H_DIM) + i];
    context[i] = s;
}

// ---------------------------------------------------------------------------
extern "C" void kernel_launch(void* const* d_in, const int* in_sizes, int n_in,
                              void* d_out, int out_size)
{
    (void)in_sizes; (void)n_in; (void)out_size;
    const float* hidden = (const float*)d_in[0];
    const int*   mask   = (const int*)d_in[1];
    const float* W      = (const float*)d_in[2];
    const float* bias   = (const float*)d_in[3];
    const float* v      = (const float*)d_in[4];

    float* context = (float*)d_out;                          // [B, H]
    float* weights = (float*)d_out + (size_t)B_DIM * H_DIM;  // [B, S]

    cudaFuncSetAttribute(scores_gemm_mma,
                         cudaFuncAttributeMaxDynamicSharedMemorySize, GEMM_SMEM);

    convert_w_kernel<<<NTILES * NKCH, 256>>>(W);

    scores_gemm_mma<<<dim3(NMTILES, NTILES), 512, GEMM_SMEM>>>(hidden, bias, v);

    softmax_kernel<<<B_DIM, 256>>>(mask, weights);

    context_part_kernel<<<dim3(SCHUNK, B_DIM), 128>>>(hidden, weights);
    context_reduce_kernel<<<(B_DIM * H_DIM) / 256, 256>>>(context);
}

// round 10
// speedup vs baseline: 1.8308x; 1.4180x over previous
#include <cuda_runtime.h>
#include <cuda_bf16.h>
#include <cuda_fp16.h>
#include <cstdint>

// ---------------------------------------------------------------------------
// Problem dims
// ---------------------------------------------------------------------------
#define B_DIM 64
#define S_DIM 2048
#define H_DIM 512
#define M_DIM (B_DIM * S_DIM)   // 131072
#define NEG_INF_SCORE (-1e9f)

// GEMM tiling: CTA 128x128, K chunks of 64, 16 warps (4m x 4n), warp 32x32
#define KC 64
#define NKCH (H_DIM / KC)        // 8
#define MT 128
#define NT 128
#define NTILES (H_DIM / NT)      // 4
#define NMTILES (M_DIM / MT)     // 1024
#define NSTAGE 4

// SMEM stage layout (bytes): A fp16 16KB, B fp16 16KB
#define A_OFF 0
#define B_OFF 16384
#define STAGE 32768
#define GEMM_SMEM (NSTAGE * STAGE)   // 128 KB

// Context s-chunking
#define SCHUNK 32
#define S_PER_CHUNK (S_DIM / SCHUNK)  // 64

// ---------------------------------------------------------------------------
// Device scratch (static only). W fp16 pre-swizzled tiles: tile (nt,c)
// is 128 n-rows x 64 k, 16 KB, SW128-swizzled 128B rows.
// ---------------------------------------------------------------------------
__device__ __align__(16) __half g_Wh[H_DIM * H_DIM];
__device__ float g_score_part[NTILES * M_DIM];
__device__ float g_ctx_part[SCHUNK * B_DIM * H_DIM];

__device__ __forceinline__ uint32_t smem_u32(const void* p) {
    uint32_t a;
    asm("{ .reg .u64 t; cvta.to.shared.u64 t, %1; cvt.u32.u64 %0, t; }" : "=r"(a) : "l"(p));
    return a;
}
// SW128 swizzle of (row-byte-base, column-byte-offset<128). Exact and in-bounds.
__device__ __forceinline__ uint32_t swz(uint32_t rowoff, uint32_t col) {
    return rowoff + (col ^ ((rowoff >> 3) & 0x70));
}

__device__ __forceinline__ void cp_async16(uint32_t dst, const void* src) {
    asm volatile("cp.async.cg.shared.global [%0], [%1], 16;"
                 :: "r"(dst), "l"(__cvta_generic_to_global(src)) : "memory");
}
__device__ __forceinline__ void cp_async_commit() {
    asm volatile("cp.async.commit_group;" ::: "memory");
}

__device__ __forceinline__ void ldsm_x4(uint32_t* r, uint32_t addr) {
    asm volatile("ldmatrix.sync.aligned.m8n8.x4.shared.b16 {%0,%1,%2,%3}, [%4];"
                 : "=r"(r[0]), "=r"(r[1]), "=r"(r[2]), "=r"(r[3]) : "r"(addr));
}

__device__ __forceinline__ void mma16816(float* d, const uint32_t* a, uint32_t b0, uint32_t b1) {
    asm volatile(
        "mma.sync.aligned.m16n8k16.row.col.f32.f16.f16.f32 "
        "{%0,%1,%2,%3}, {%4,%5,%6,%7}, {%8,%9}, {%0,%1,%2,%3};"
        : "+f"(d[0]), "+f"(d[1]), "+f"(d[2]), "+f"(d[3])
        : "r"(a[0]), "r"(a[1]), "r"(a[2]), "r"(a[3]), "r"(b0), "r"(b1));
}

// pack 2 floats -> one fp16x2 register
__device__ __forceinline__ uint32_t pack_h2(float x, float y) {
    __half2 h = __floats2half2_rn(x, y);
    return *reinterpret_cast<uint32_t*>(&h);
}

// ---------------------------------------------------------------------------
// W pre-convert: fp32 [512(n),512(k)] -> pre-swizzled fp16 tiles
// grid: 32 blocks (nt*8+c), 256 threads
// ---------------------------------------------------------------------------
__global__ void __launch_bounds__(256)
convert_w_kernel(const float* __restrict__ W)
{
    const int nt = blockIdx.x >> 3;
    const int c  = blockIdx.x & 7;
    const int tid = threadIdx.x;
    const int row = tid >> 1;              // 0..127 (n within tile)
    const int kh  = (tid & 1) * 32;        // k element offset half-row

    const float* src = W + (size_t)(nt * NT + row) * H_DIM + c * KC + kh;
    char* dst = (char*)g_Wh + (size_t)(blockIdx.x) * 16384;

    const uint32_t rowoff = (uint32_t)row * 128;
    #pragma unroll
    for (int i = 0; i < 8; i++) {
        float4 xv = *(const float4*)(src + i * 4);
        uint2 hv;
        hv.x = pack_h2(xv.x, xv.y);
        hv.y = pack_h2(xv.z, xv.w);
        const uint32_t off = swz(rowoff, (uint32_t)(kh * 2 + i * 8));
        *(uint2*)(dst + off) = hv;
    }
}

// ---------------------------------------------------------------------------
// Scores GEMM via mma.sync fp16 (single term, fp32 accum), fused tanh.v
// reduce. grid (1024, 4), 512 threads / 16 warps, 4-stage pipeline.
// ---------------------------------------------------------------------------
__global__ void __launch_bounds__(512, 1)
scores_gemm_mma(const float* __restrict__ X,
                const float* __restrict__ bias,
                const float* __restrict__ v)
{
    extern __shared__ char smem[];
    __shared__ float red[4][MT];

    const uint32_t sb = smem_u32(smem);
    const int tid  = threadIdx.x;
    const int wid  = tid >> 5;
    const int lane = tid & 31;
    const int wm   = wid & 3;      // warp m index (0..3)
    const int wn   = wid >> 2;     // warp n index (0..3)
    const int t  = blockIdx.x;     // m-tile
    const int nt = blockIdx.y;     // n-tile

    // A global mapping: thread owns row = tid>>2, k-quarter = (tid&3)*16 elems
    const int arow = tid >> 2;                // 0..127
    const int akq  = (tid & 3) * 16;          // k element offset (16 elems)
    const float* aptr = X + (size_t)(t * MT + arow) * H_DIM + akq;
    const uint32_t a_rowoff = (uint32_t)arow * 128;
    const uint32_t a_colbase = (uint32_t)(akq * 2);   // 0,32,64,96 bytes (fp16)

    // B global tiles (pre-swizzled 16KB blobs)
    const char* bg = (const char*)g_Wh + (size_t)(nt * NKCH) * 16384;

    // ldmatrix row bases; column = kb + ks*32 composed inside the swizzle
    const int lrow = lane & 15;
    const uint32_t kb = (lane >> 4) * 16;
    uint32_t a_rowb[2], b_rowb[2];
    #pragma unroll
    for (int mi = 0; mi < 2; mi++)
        a_rowb[mi] = (uint32_t)(wm * 32 + mi * 16 + lrow) * 128;
    #pragma unroll
    for (int np = 0; np < 2; np++)
        b_rowb[np] = (uint32_t)(wn * 32 + np * 16 + lrow) * 128;

    float acc[2][4][4];
    #pragma unroll
    for (int mi = 0; mi < 2; mi++)
        #pragma unroll
        for (int ni = 0; ni < 4; ni++)
            #pragma unroll
            for (int j = 0; j < 4; j++) acc[mi][ni][j] = 0.f;

    // helper lambdas ------------------------------------------------------
    auto b_load = [&](int c) {   // cp.async B for chunk c into stage c%4
        const uint32_t stb = sb + (uint32_t)(c % NSTAGE) * STAGE;
        const char* bh = bg + (size_t)c * 16384;
        #pragma unroll
        for (int it = 0; it < 2; it++)
            cp_async16(stb + B_OFF + tid * 16 + it * 8192, bh + tid * 16 + it * 8192);
        cp_async_commit();
    };
    auto a_ldg = [&](int c, float4* areg) {
        #pragma unroll
        for (int i = 0; i < 4; i++)
            areg[i] = *(const float4*)(aptr + c * KC + i * 4);
    };
    auto a_sts = [&](int c, const float4* areg) {   // fp16 single-rounded
        char* st = smem + (size_t)(c % NSTAGE) * STAGE;
        uint4 v0, v1;
        v0.x = pack_h2(areg[0].x, areg[0].y);
        v0.y = pack_h2(areg[0].z, areg[0].w);
        v0.z = pack_h2(areg[1].x, areg[1].y);
        v0.w = pack_h2(areg[1].z, areg[1].w);
        v1.x = pack_h2(areg[2].x, areg[2].y);
        v1.y = pack_h2(areg[2].z, areg[2].w);
        v1.z = pack_h2(areg[3].x, areg[3].y);
        v1.w = pack_h2(areg[3].z, areg[3].w);
        *(uint4*)(st + A_OFF + swz(a_rowoff, a_colbase))      = v0;
        *(uint4*)(st + A_OFF + swz(a_rowoff, a_colbase + 16)) = v1;
    };

    // ---- prologue: chunks 0, 1, 2 ----
    {
        b_load(0); b_load(1); b_load(2);
        float4 ar[4];
        a_ldg(0, ar); a_sts(0, ar);
        a_ldg(1, ar); a_sts(1, ar);
        a_ldg(2, ar); a_sts(2, ar);
    }
    __syncthreads();

    for (int c = 0; c < NKCH; c++) {
        if (c < NKCH - 2)       asm volatile("cp.async.wait_group 2;" ::: "memory");
        else if (c == NKCH - 2) asm volatile("cp.async.wait_group 1;" ::: "memory");
        else                    asm volatile("cp.async.wait_group 0;" ::: "memory");
        __syncthreads();

        float4 areg[4];
        if (c + 3 < NKCH) {
            b_load(c + 3);          // async, overlaps compute below
            a_ldg(c + 3, areg);     // latency hidden by compute
        }

        // ---- compute chunk c, fragment ping-pong over ks ----
        const uint32_t st = sb + (uint32_t)(c % NSTAGE) * STAGE;
        uint32_t ah[2][2][4], bh[2][2][4];

        // load ks=0 fragments into buffer 0
        {
            const uint32_t kcol = kb;
            #pragma unroll
            for (int mi = 0; mi < 2; mi++)
                ldsm_x4(ah[0][mi], st + A_OFF + swz(a_rowb[mi], kcol));
            #pragma unroll
            for (int np = 0; np < 2; np++)
                ldsm_x4(bh[0][np], st + B_OFF + swz(b_rowb[np], kcol));
        }

        #pragma unroll
        for (int ks = 0; ks < KC / 16; ks++) {
            const int cur = ks & 1;
            const int nxt = cur ^ 1;
            if (ks + 1 < KC / 16) {
                const uint32_t kcol = kb + (ks + 1) * 32;
                #pragma unroll
                for (int mi = 0; mi < 2; mi++)
                    ldsm_x4(ah[nxt][mi], st + A_OFF + swz(a_rowb[mi], kcol));
                #pragma unroll
                for (int np = 0; np < 2; np++)
                    ldsm_x4(bh[nxt][np], st + B_OFF + swz(b_rowb[np], kcol));
            }
            #pragma unroll
            for (int mi = 0; mi < 2; mi++)
                #pragma unroll
                for (int np = 0; np < 2; np++)
                    #pragma unroll
                    for (int hf = 0; hf < 2; hf++)
                        mma16816(acc[mi][np * 2 + hf], ah[cur][mi],
                                 bh[cur][np][hf], bh[cur][np][hf + 2]);
        }

        if (c + 3 < NKCH)
            a_sts(c + 3, areg);     // stage (c+3)%4 free (consumed at c-1)
    }

    // ---- epilogue: rsum[row] = sum_n v[n]*tanh(acc + b[n]) ----
    const int ncol0 = nt * NT + wn * 32 + (lane & 3) * 2;
    float rs[2][2] = {{0.f, 0.f}, {0.f, 0.f}};
    #pragma unroll
    for (int np = 0; np < 2; np++) {
        #pragma unroll
        for (int hf = 0; hf < 2; hf++) {
            #pragma unroll
            for (int cc = 0; cc < 2; cc++) {
                const int col = ncol0 + np * 16 + hf * 8 + cc;
                const float bb = bias[col];
                const float vv = v[col];
                #pragma unroll
                for (int mi = 0; mi < 2; mi++) {
                    float x0 = acc[mi][np * 2 + hf][cc] + bb;       // row groupID
                    float x1 = acc[mi][np * 2 + hf][cc + 2] + bb;   // row groupID+8
                    float t0, t1;
                    asm("tanh.approx.f32 %0, %1;" : "=f"(t0) : "f"(x0));
                    asm("tanh.approx.f32 %0, %1;" : "=f"(t1) : "f"(x1));
                    rs[mi][0] = fmaf(t0, vv, rs[mi][0]);
                    rs[mi][1] = fmaf(t1, vv, rs[mi][1]);
                }
            }
        }
    }
    // reduce across the 4 lanes sharing a row (lane bits 0-1)
    #pragma unroll
    for (int mi = 0; mi < 2; mi++)
        #pragma unroll
        for (int h = 0; h < 2; h++) {
            rs[mi][h] += __shfl_xor_sync(0xffffffffu, rs[mi][h], 1);
            rs[mi][h] += __shfl_xor_sync(0xffffffffu, rs[mi][h], 2);
        }

    __syncthreads();   // all compute done before red[] use
    if ((lane & 3) == 0) {
        #pragma unroll
        for (int mi = 0; mi < 2; mi++)
            #pragma unroll
            for (int h = 0; h < 2; h++)
                red[wn][wm * 32 + mi * 16 + h * 8 + (lane >> 2)] = rs[mi][h];
    }
    __syncthreads();
    if (tid < MT) {
        float s = red[0][tid] + red[1][tid] + red[2][tid] + red[3][tid];
        g_score_part[(size_t)nt * M_DIM + (size_t)t * MT + tid] = s;
    }
}

// ---------------------------------------------------------------------------
// Softmax (folds 4 n-tile partials), mask as int32
// ---------------------------------------------------------------------------
__device__ __forceinline__ float warp_max(float v) {
    #pragma unroll
    for (int o = 16; o > 0; o >>= 1) v = fmaxf(v, __shfl_xor_sync(0xffffffffu, v, o));
    return v;
}
__device__ __forceinline__ float warp_sum(float v) {
    #pragma unroll
    for (int o = 16; o > 0; o >>= 1) v += __shfl_xor_sync(0xffffffffu, v, o);
    return v;
}

__global__ void __launch_bounds__(256)
softmax_kernel(const int* __restrict__ mask, float* __restrict__ weights)
{
    const int b    = blockIdx.x;
    const int tid  = threadIdx.x;
    const int lane = tid & 31;
    const int wid  = tid >> 5;

    __shared__ float red[8];

    float vals[8];
    float mx = -3.4e38f;
    #pragma unroll
    for (int i = 0; i < 8; i++) {
        const size_t m = (size_t)b * S_DIM + tid + i * 256;
        float sc = 0.f;
        #pragma unroll
        for (int n = 0; n < NTILES; n++)
            sc += g_score_part[(size_t)n * M_DIM + m];
        if (mask[m] == 0) sc = NEG_INF_SCORE;
        vals[i] = sc;
        mx = fmaxf(mx, sc);
    }

    mx = warp_max(mx);
    if (lane == 0) red[wid] = mx;
    __syncthreads();
    float bmax = red[0];
    #pragma unroll
    for (int i = 1; i < 8; i++) bmax = fmaxf(bmax, red[i]);
    __syncthreads();

    float s_sum = 0.f;
    #pragma unroll
    for (int i = 0; i < 8; i++) {
        vals[i] = __expf(vals[i] - bmax);
        s_sum += vals[i];
    }
    s_sum = warp_sum(s_sum);
    if (lane == 0) red[wid] = s_sum;
    __syncthreads();
    float total = red[0];
    #pragma unroll
    for (int i = 1; i < 8; i++) total += red[i];

    const float inv = 1.0f / total;
    #pragma unroll
    for (int i = 0; i < 8; i++)
        weights[(size_t)b * S_DIM + tid + i * 256] = vals[i] * inv;
}

// ---------------------------------------------------------------------------
// Context: weighted sum over S (memory-bound second pass over hidden)
// ---------------------------------------------------------------------------
__global__ void __launch_bounds__(128)
context_part_kernel(const float* __restrict__ hidden, const float* __restrict__ weights)
{
    const int sc = blockIdx.x;          // 0..31
    const int b  = blockIdx.y;          // 0..63
    const int h4 = threadIdx.x * 4;

    const int s0 = sc * S_PER_CHUNK;
    const float* wrow  = weights + (size_t)b * S_DIM + s0;
    const float* hbase = hidden + ((size_t)b * S_DIM + s0) * H_DIM + h4;

    float4 acc = make_float4(0.f, 0.f, 0.f, 0.f);
    #pragma unroll 8
    for (int s = 0; s < S_PER_CHUNK; s++) {
        const float w = wrow[s];
        float4 hv = *(const float4*)(hbase + (size_t)s * H_DIM);
        acc.x = fmaf(w, hv.x, acc.x);
        acc.y = fmaf(w, hv.y, acc.y);
        acc.z = fmaf(w, hv.z, acc.z);
        acc.w = fmaf(w, hv.w, acc.w);
    }
    *(float4*)(g_ctx_part + ((size_t)(sc * B_DIM + b)) * H_DIM + h4) = acc;
}

__global__ void __launch_bounds__(256)
context_reduce_kernel(float* __restrict__ context)
{
    const int i = blockIdx.x * blockDim.x + threadIdx.x;
    float s = 0.f;
    #pragma unroll
    for (int n = 0; n < SCHUNK; n++)
        s += g_ctx_part[(size_t)n * (B_DIM * H_DIM) + i];
    context[i] = s;
}

// ---------------------------------------------------------------------------
extern "C" void kernel_launch(void* const* d_in, const int* in_sizes, int n_in,
                              void* d_out, int out_size)
{
    (void)in_sizes; (void)n_in; (void)out_size;
    const float* hidden = (const float*)d_in[0];
    const int*   mask   = (const int*)d_in[1];
    const float* W      = (const float*)d_in[2];
    const float* bias   = (const float*)d_in[3];
    const float* v      = (const float*)d_in[4];

    float* context = (float*)d_out;                          // [B, H]
    float* weights = (float*)d_out + (size_t)B_DIM * H_DIM;  // [B, S]

    cudaFuncSetAttribute(scores_gemm_mma,
                         cudaFuncAttributeMaxDynamicSharedMemorySize, GEMM_SMEM);

    convert_w_kernel<<<NTILES * NKCH, 256>>>(W);

    scores_gemm_mma<<<dim3(NMTILES, NTILES), 512, GEMM_SMEM>>>(hidden, bias, v);

    softmax_kernel<<<B_DIM, 256>>>(mask, weights);

    context_part_kernel<<<dim3(SCHUNK, B_DIM), 128>>>(hidden, weights);
    context_reduce_kernel<<<(B_DIM * H_DIM) / 256, 256>>>(context);
}

// round 11
// speedup vs baseline: 1.8584x; 1.0151x over previous
#include <cuda_runtime.h>
#include <cuda_bf16.h>
#include <cuda_fp16.h>
#include <cstdint>

// ---------------------------------------------------------------------------
// Problem dims
// ---------------------------------------------------------------------------
#define B_DIM 64
#define S_DIM 2048
#define H_DIM 512
#define M_DIM (B_DIM * S_DIM)   // 131072
#define NEG_INF_SCORE (-1e9f)

// GEMM tiling: CTA 128x128, K chunks of 64, 16 warps (4m x 4n), warp 32x32
#define KC 64
#define NKCH (H_DIM / KC)        // 8
#define MT 128
#define NT 128
#define NTILES (H_DIM / NT)      // 4
#define NMTILES (M_DIM / MT)     // 1024
#define NSTAGE 4

// SMEM stage layout (bytes): A fp16 16KB, B fp16 16KB
#define A_OFF 0
#define B_OFF 16384
#define STAGE 32768
#define GEMM_SMEM (NSTAGE * STAGE)   // 128 KB

// Context s-chunking
#define SCHUNK 32
#define S_PER_CHUNK (S_DIM / SCHUNK)  // 64

// ---------------------------------------------------------------------------
// Device scratch (static only). W fp16 pre-swizzled tiles: tile (nt,c)
// is 128 n-rows x 64 k, 16 KB, SW128-swizzled 128B rows.
// ---------------------------------------------------------------------------
__device__ __align__(16) __half g_Wh[H_DIM * H_DIM];
__device__ float g_score_part[NTILES * M_DIM];
__device__ float g_ctx_part[SCHUNK * B_DIM * H_DIM];

__device__ __forceinline__ uint32_t smem_u32(const void* p) {
    uint32_t a;
    asm("{ .reg .u64 t; cvta.to.shared.u64 t, %1; cvt.u32.u64 %0, t; }" : "=r"(a) : "l"(p));
    return a;
}
// SW128 swizzle of (row-byte-base, column-byte-offset<128). Exact and in-bounds.
__device__ __forceinline__ uint32_t swz(uint32_t rowoff, uint32_t col) {
    return rowoff + (col ^ ((rowoff >> 3) & 0x70));
}

__device__ __forceinline__ void cp_async16(uint32_t dst, const void* src) {
    asm volatile("cp.async.cg.shared.global [%0], [%1], 16;"
                 :: "r"(dst), "l"(__cvta_generic_to_global(src)) : "memory");
}
__device__ __forceinline__ void cp_async_commit() {
    asm volatile("cp.async.commit_group;" ::: "memory");
}

__device__ __forceinline__ void ldsm_x4(uint32_t* r, uint32_t addr) {
    asm volatile("ldmatrix.sync.aligned.m8n8.x4.shared.b16 {%0,%1,%2,%3}, [%4];"
                 : "=r"(r[0]), "=r"(r[1]), "=r"(r[2]), "=r"(r[3]) : "r"(addr));
}

__device__ __forceinline__ void mma16816(float* d, const uint32_t* a, uint32_t b0, uint32_t b1) {
    asm volatile(
        "mma.sync.aligned.m16n8k16.row.col.f32.f16.f16.f32 "
        "{%0,%1,%2,%3}, {%4,%5,%6,%7}, {%8,%9}, {%0,%1,%2,%3};"
        : "+f"(d[0]), "+f"(d[1]), "+f"(d[2]), "+f"(d[3])
        : "r"(a[0]), "r"(a[1]), "r"(a[2]), "r"(a[3]), "r"(b0), "r"(b1));
}

// pack 2 floats -> one fp16x2 register
__device__ __forceinline__ uint32_t pack_h2(float x, float y) {
    __half2 h = __floats2half2_rn(x, y);
    return *reinterpret_cast<uint32_t*>(&h);
}

// ---------------------------------------------------------------------------
// W pre-convert: fp32 [512(n),512(k)] -> pre-swizzled fp16 tiles
// grid: 32 blocks (nt*8+c), 256 threads
// ---------------------------------------------------------------------------
__global__ void __launch_bounds__(256)
convert_w_kernel(const float* __restrict__ W)
{
    const int nt = blockIdx.x >> 3;
    const int c  = blockIdx.x & 7;
    const int tid = threadIdx.x;
    const int row = tid >> 1;              // 0..127 (n within tile)
    const int kh  = (tid & 1) * 32;        // k element offset half-row

    const float* src = W + (size_t)(nt * NT + row) * H_DIM + c * KC + kh;
    char* dst = (char*)g_Wh + (size_t)(blockIdx.x) * 16384;

    const uint32_t rowoff = (uint32_t)row * 128;
    #pragma unroll
    for (int i = 0; i < 8; i++) {
        float4 xv = *(const float4*)(src + i * 4);
        uint2 hv;
        hv.x = pack_h2(xv.x, xv.y);
        hv.y = pack_h2(xv.z, xv.w);
        const uint32_t off = swz(rowoff, (uint32_t)(kh * 2 + i * 8));
        *(uint2*)(dst + off) = hv;
    }
}

// ---------------------------------------------------------------------------
// Scores GEMM via mma.sync fp16 (single term, fp32 accum), fused tanh.v
// reduce. grid (4 n-tiles, 1024 m-tiles): the 4 CTAs sharing an m-tile's X
// rows are ADJACENT in schedule order -> X tile stays L2-resident and is
// fetched from DRAM only once (was 4x with the swapped grid).
// 512 threads / 16 warps, 4-stage pipeline.
// ---------------------------------------------------------------------------
__global__ void __launch_bounds__(512, 1)
scores_gemm_mma(const float* __restrict__ X,
                const float* __restrict__ bias,
                const float* __restrict__ v)
{
    extern __shared__ char smem[];
    __shared__ float red[4][MT];

    const uint32_t sb = smem_u32(smem);
    const int tid  = threadIdx.x;
    const int wid  = tid >> 5;
    const int lane = tid & 31;
    const int wm   = wid & 3;      // warp m index (0..3)
    const int wn   = wid >> 2;     // warp n index (0..3)
    const int nt = blockIdx.x;     // n-tile (fast dim -> adjacent CTAs share X)
    const int t  = blockIdx.y;     // m-tile

    // A global mapping: thread owns row = tid>>2, k-quarter = (tid&3)*16 elems
    const int arow = tid >> 2;                // 0..127
    const int akq  = (tid & 3) * 16;          // k element offset (16 elems)
    const float* aptr = X + (size_t)(t * MT + arow) * H_DIM + akq;
    const uint32_t a_rowoff = (uint32_t)arow * 128;
    const uint32_t a_colbase = (uint32_t)(akq * 2);   // 0,32,64,96 bytes (fp16)

    // B global tiles (pre-swizzled 16KB blobs)
    const char* bg = (const char*)g_Wh + (size_t)(nt * NKCH) * 16384;

    // ldmatrix row bases; column = kb + ks*32 composed inside the swizzle
    const int lrow = lane & 15;
    const uint32_t kb = (lane >> 4) * 16;
    uint32_t a_rowb[2], b_rowb[2];
    #pragma unroll
    for (int mi = 0; mi < 2; mi++)
        a_rowb[mi] = (uint32_t)(wm * 32 + mi * 16 + lrow) * 128;
    #pragma unroll
    for (int np = 0; np < 2; np++)
        b_rowb[np] = (uint32_t)(wn * 32 + np * 16 + lrow) * 128;

    float acc[2][4][4];
    #pragma unroll
    for (int mi = 0; mi < 2; mi++)
        #pragma unroll
        for (int ni = 0; ni < 4; ni++)
            #pragma unroll
            for (int j = 0; j < 4; j++) acc[mi][ni][j] = 0.f;

    // helper lambdas ------------------------------------------------------
    auto b_load = [&](int c) {   // cp.async B for chunk c into stage c%4
        const uint32_t stb = sb + (uint32_t)(c % NSTAGE) * STAGE;
        const char* bh = bg + (size_t)c * 16384;
        #pragma unroll
        for (int it = 0; it < 2; it++)
            cp_async16(stb + B_OFF + tid * 16 + it * 8192, bh + tid * 16 + it * 8192);
        cp_async_commit();
    };
    auto a_ldg = [&](int c, float4* areg) {
        #pragma unroll
        for (int i = 0; i < 4; i++)
            areg[i] = *(const float4*)(aptr + c * KC + i * 4);
    };
    auto a_sts = [&](int c, const float4* areg) {   // fp16 single-rounded
        char* st = smem + (size_t)(c % NSTAGE) * STAGE;
        uint4 v0, v1;
        v0.x = pack_h2(areg[0].x, areg[0].y);
        v0.y = pack_h2(areg[0].z, areg[0].w);
        v0.z = pack_h2(areg[1].x, areg[1].y);
        v0.w = pack_h2(areg[1].z, areg[1].w);
        v1.x = pack_h2(areg[2].x, areg[2].y);
        v1.y = pack_h2(areg[2].z, areg[2].w);
        v1.z = pack_h2(areg[3].x, areg[3].y);
        v1.w = pack_h2(areg[3].z, areg[3].w);
        *(uint4*)(st + A_OFF + swz(a_rowoff, a_colbase))      = v0;
        *(uint4*)(st + A_OFF + swz(a_rowoff, a_colbase + 16)) = v1;
    };

    // ---- prologue: chunks 0, 1, 2 ----
    {
        b_load(0); b_load(1); b_load(2);
        float4 ar[4];
        a_ldg(0, ar); a_sts(0, ar);
        a_ldg(1, ar); a_sts(1, ar);
        a_ldg(2, ar); a_sts(2, ar);
    }
    __syncthreads();

    for (int c = 0; c < NKCH; c++) {
        if (c < NKCH - 2)       asm volatile("cp.async.wait_group 2;" ::: "memory");
        else if (c == NKCH - 2) asm volatile("cp.async.wait_group 1;" ::: "memory");
        else                    asm volatile("cp.async.wait_group 0;" ::: "memory");
        __syncthreads();

        float4 areg[4];
        if (c + 3 < NKCH) {
            b_load(c + 3);          // async, overlaps compute below
            a_ldg(c + 3, areg);     // latency hidden by compute
        }

        // ---- compute chunk c, fragment ping-pong over ks ----
        const uint32_t st = sb + (uint32_t)(c % NSTAGE) * STAGE;
        uint32_t ah[2][2][4], bh[2][2][4];

        // load ks=0 fragments into buffer 0
        {
            const uint32_t kcol = kb;
            #pragma unroll
            for (int mi = 0; mi < 2; mi++)
                ldsm_x4(ah[0][mi], st + A_OFF + swz(a_rowb[mi], kcol));
            #pragma unroll
            for (int np = 0; np < 2; np++)
                ldsm_x4(bh[0][np], st + B_OFF + swz(b_rowb[np], kcol));
        }

        #pragma unroll
        for (int ks = 0; ks < KC / 16; ks++) {
            const int cur = ks & 1;
            const int nxt = cur ^ 1;
            if (ks + 1 < KC / 16) {
                const uint32_t kcol = kb + (ks + 1) * 32;
                #pragma unroll
                for (int mi = 0; mi < 2; mi++)
                    ldsm_x4(ah[nxt][mi], st + A_OFF + swz(a_rowb[mi], kcol));
                #pragma unroll
                for (int np = 0; np < 2; np++)
                    ldsm_x4(bh[nxt][np], st + B_OFF + swz(b_rowb[np], kcol));
            }
            #pragma unroll
            for (int mi = 0; mi < 2; mi++)
                #pragma unroll
                for (int np = 0; np < 2; np++)
                    #pragma unroll
                    for (int hf = 0; hf < 2; hf++)
                        mma16816(acc[mi][np * 2 + hf], ah[cur][mi],
                                 bh[cur][np][hf], bh[cur][np][hf + 2]);
        }

        if (c + 3 < NKCH)
            a_sts(c + 3, areg);     // stage (c+3)%4 free (consumed at c-1)
    }

    // ---- epilogue: rsum[row] = sum_n v[n]*tanh(acc + b[n]) ----
    const int ncol0 = nt * NT + wn * 32 + (lane & 3) * 2;
    float rs[2][2] = {{0.f, 0.f}, {0.f, 0.f}};
    #pragma unroll
    for (int np = 0; np < 2; np++) {
        #pragma unroll
        for (int hf = 0; hf < 2; hf++) {
            #pragma unroll
            for (int cc = 0; cc < 2; cc++) {
                const int col = ncol0 + np * 16 + hf * 8 + cc;
                const float bb = bias[col];
                const float vv = v[col];
                #pragma unroll
                for (int mi = 0; mi < 2; mi++) {
                    float x0 = acc[mi][np * 2 + hf][cc] + bb;       // row groupID
                    float x1 = acc[mi][np * 2 + hf][cc + 2] + bb;   // row groupID+8
                    float t0, t1;
                    asm("tanh.approx.f32 %0, %1;" : "=f"(t0) : "f"(x0));
                    asm("tanh.approx.f32 %0, %1;" : "=f"(t1) : "f"(x1));
                    rs[mi][0] = fmaf(t0, vv, rs[mi][0]);
                    rs[mi][1] = fmaf(t1, vv, rs[mi][1]);
                }
            }
        }
    }
    // reduce across the 4 lanes sharing a row (lane bits 0-1)
    #pragma unroll
    for (int mi = 0; mi < 2; mi++)
        #pragma unroll
        for (int h = 0; h < 2; h++) {
            rs[mi][h] += __shfl_xor_sync(0xffffffffu, rs[mi][h], 1);
            rs[mi][h] += __shfl_xor_sync(0xffffffffu, rs[mi][h], 2);
        }

    __syncthreads();   // all compute done before red[] use
    if ((lane & 3) == 0) {
        #pragma unroll
        for (int mi = 0; mi < 2; mi++)
            #pragma unroll
            for (int h = 0; h < 2; h++)
                red[wn][wm * 32 + mi * 16 + h * 8 + (lane >> 2)] = rs[mi][h];
    }
    __syncthreads();
    if (tid < MT) {
        float s = red[0][tid] + red[1][tid] + red[2][tid] + red[3][tid];
        g_score_part[(size_t)nt * M_DIM + (size_t)t * MT + tid] = s;
    }
}

// ---------------------------------------------------------------------------
// Softmax (folds 4 n-tile partials), mask as int32
// ---------------------------------------------------------------------------
__device__ __forceinline__ float warp_max(float v) {
    #pragma unroll
    for (int o = 16; o > 0; o >>= 1) v = fmaxf(v, __shfl_xor_sync(0xffffffffu, v, o));
    return v;
}
__device__ __forceinline__ float warp_sum(float v) {
    #pragma unroll
    for (int o = 16; o > 0; o >>= 1) v += __shfl_xor_sync(0xffffffffu, v, o);
    return v;
}

__global__ void __launch_bounds__(256)
softmax_kernel(const int* __restrict__ mask, float* __restrict__ weights)
{
    const int b    = blockIdx.x;
    const int tid  = threadIdx.x;
    const int lane = tid & 31;
    const int wid  = tid >> 5;

    __shared__ float red[8];

    float vals[8];
    float mx = -3.4e38f;
    #pragma unroll
    for (int i = 0; i < 8; i++) {
        const size_t m = (size_t)b * S_DIM + tid + i * 256;
        float sc = 0.f;
        #pragma unroll
        for (int n = 0; n < NTILES; n++)
            sc += g_score_part[(size_t)n * M_DIM + m];
        if (mask[m] == 0) sc = NEG_INF_SCORE;
        vals[i] = sc;
        mx = fmaxf(mx, sc);
    }

    mx = warp_max(mx);
    if (lane == 0) red[wid] = mx;
    __syncthreads();
    float bmax = red[0];
    #pragma unroll
    for (int i = 1; i < 8; i++) bmax = fmaxf(bmax, red[i]);
    __syncthreads();

    float s_sum = 0.f;
    #pragma unroll
    for (int i = 0; i < 8; i++) {
        vals[i] = __expf(vals[i] - bmax);
        s_sum += vals[i];
    }
    s_sum = warp_sum(s_sum);
    if (lane == 0) red[wid] = s_sum;
    __syncthreads();
    float total = red[0];
    #pragma unroll
    for (int i = 1; i < 8; i++) total += red[i];

    const float inv = 1.0f / total;
    #pragma unroll
    for (int i = 0; i < 8; i++)
        weights[(size_t)b * S_DIM + tid + i * 256] = vals[i] * inv;
}

// ---------------------------------------------------------------------------
// Context: weighted sum over S (memory-bound second pass over hidden)
// ---------------------------------------------------------------------------
__global__ void __launch_bounds__(128)
context_part_kernel(const float* __restrict__ hidden, const float* __restrict__ weights)
{
    const int sc = blockIdx.x;          // 0..31
    const int b  = blockIdx.y;          // 0..63
    const int h4 = threadIdx.x * 4;

    const int s0 = sc * S_PER_CHUNK;
    const float* wrow  = weights + (size_t)b * S_DIM + s0;
    const float* hbase = hidden + ((size_t)b * S_DIM + s0) * H_DIM + h4;

    float4 acc = make_float4(0.f, 0.f, 0.f, 0.f);
    #pragma unroll 8
    for (int s = 0; s < S_PER_CHUNK; s++) {
        const float w = wrow[s];
        float4 hv = *(const float4*)(hbase + (size_t)s * H_DIM);
        acc.x = fmaf(w, hv.x, acc.x);
        acc.y = fmaf(w, hv.y, acc.y);
        acc.z = fmaf(w, hv.z, acc.z);
        acc.w = fmaf(w, hv.w, acc.w);
    }
    *(float4*)(g_ctx_part + ((size_t)(sc * B_DIM + b)) * H_DIM + h4) = acc;
}

__global__ void __launch_bounds__(256)
context_reduce_kernel(float* __restrict__ context)
{
    const int i = blockIdx.x * blockDim.x + threadIdx.x;
    float s = 0.f;
    #pragma unroll
    for (int n = 0; n < SCHUNK; n++)
        s += g_ctx_part[(size_t)n * (B_DIM * H_DIM) + i];
    context[i] = s;
}

// ---------------------------------------------------------------------------
extern "C" void kernel_launch(void* const* d_in, const int* in_sizes, int n_in,
                              void* d_out, int out_size)
{
    (void)in_sizes; (void)n_in; (void)out_size;
    const float* hidden = (const float*)d_in[0];
    const int*   mask   = (const int*)d_in[1];
    const float* W      = (const float*)d_in[2];
    const float* bias   = (const float*)d_in[3];
    const float* v      = (const float*)d_in[4];

    float* context = (float*)d_out;                          // [B, H]
    float* weights = (float*)d_out + (size_t)B_DIM * H_DIM;  // [B, S]

    cudaFuncSetAttribute(scores_gemm_mma,
                         cudaFuncAttributeMaxDynamicSharedMemorySize, GEMM_SMEM);

    convert_w_kernel<<<NTILES * NKCH, 256>>>(W);

    scores_gemm_mma<<<dim3(NTILES, NMTILES), 512, GEMM_SMEM>>>(hidden, bias, v);

    softmax_kernel<<<B_DIM, 256>>>(mask, weights);

    context_part_kernel<<<dim3(SCHUNK, B_DIM), 128>>>(hidden, weights);
    context_reduce_kernel<<<(B_DIM * H_DIM) / 256, 256>>>(context);
}

// round 12
// speedup vs baseline: 2.0444x; 1.1001x over previous
#include <cuda_runtime.h>
#include <cuda_bf16.h>
#include <cuda_fp16.h>
#include <cstdint>

// ---------------------------------------------------------------------------
// Problem dims
// ---------------------------------------------------------------------------
#define B_DIM 64
#define S_DIM 2048
#define H_DIM 512
#define M_DIM (B_DIM * S_DIM)   // 131072
#define NEG_INF_SCORE (-1e9f)

// GEMM tiling: CTA 128x128, K chunks of 64, 16 warps (4m x 4n), warp 32x32
#define KC 64
#define NKCH (H_DIM / KC)        // 8
#define MT 128
#define NT 128
#define NTILES (H_DIM / NT)      // 4
#define NMTILES (M_DIM / MT)     // 1024
#define NSTAGE 3

// SMEM stage layout (bytes): A fp16 16KB, B fp16 16KB
#define A_OFF 0
#define B_OFF 16384
#define STAGE 32768
#define GEMM_SMEM (NSTAGE * STAGE)   // 96 KB -> 2 CTAs/SM

// Context s-chunking
#define SCHUNK 32
#define S_PER_CHUNK (S_DIM / SCHUNK)  // 64

// ---------------------------------------------------------------------------
// Device scratch (static only).
// g_Wh / g_Xh: fp16 pre-swizzled tiles, 128 rows x 64 k each, 16 KB,
// SW128-swizzled 128B rows. X tile (t, c) at index (t*8 + c).
// ---------------------------------------------------------------------------
__device__ __align__(16) __half g_Wh[H_DIM * H_DIM];
__device__ __align__(16) __half g_Xh[(size_t)M_DIM * H_DIM];   // 128 MB
__device__ float g_score_part[NTILES * M_DIM];
__device__ __align__(16) float g_ctx_part[SCHUNK * B_DIM * H_DIM];

__device__ __forceinline__ uint32_t smem_u32(const void* p) {
    uint32_t a;
    asm("{ .reg .u64 t; cvta.to.shared.u64 t, %1; cvt.u32.u64 %0, t; }" : "=r"(a) : "l"(p));
    return a;
}
// SW128 swizzle of (row-byte-base, column-byte-offset<128). Exact and in-bounds.
__device__ __forceinline__ uint32_t swz(uint32_t rowoff, uint32_t col) {
    return rowoff + (col ^ ((rowoff >> 3) & 0x70));
}

__device__ __forceinline__ void cp_async16(uint32_t dst, const void* src) {
    asm volatile("cp.async.cg.shared.global [%0], [%1], 16;"
                 :: "r"(dst), "l"(__cvta_generic_to_global(src)) : "memory");
}
__device__ __forceinline__ void cp_async_commit() {
    asm volatile("cp.async.commit_group;" ::: "memory");
}

__device__ __forceinline__ void ldsm_x4(uint32_t* r, uint32_t addr) {
    asm volatile("ldmatrix.sync.aligned.m8n8.x4.shared.b16 {%0,%1,%2,%3}, [%4];"
                 : "=r"(r[0]), "=r"(r[1]), "=r"(r[2]), "=r"(r[3]) : "r"(addr));
}

__device__ __forceinline__ void mma16816(float* d, const uint32_t* a, uint32_t b0, uint32_t b1) {
    asm volatile(
        "mma.sync.aligned.m16n8k16.row.col.f32.f16.f16.f32 "
        "{%0,%1,%2,%3}, {%4,%5,%6,%7}, {%8,%9}, {%0,%1,%2,%3};"
        : "+f"(d[0]), "+f"(d[1]), "+f"(d[2]), "+f"(d[3])
        : "r"(a[0]), "r"(a[1]), "r"(a[2]), "r"(a[3]), "r"(b0), "r"(b1));
}

// pack 2 floats -> one fp16x2 register
__device__ __forceinline__ uint32_t pack_h2(float x, float y) {
    __half2 h = __floats2half2_rn(x, y);
    return *reinterpret_cast<uint32_t*>(&h);
}

// ---------------------------------------------------------------------------
// W pre-convert: fp32 [512(n),512(k)] -> pre-swizzled fp16 tiles
// grid: 32 blocks (nt*8+c), 256 threads
// ---------------------------------------------------------------------------
__global__ void __launch_bounds__(256)
convert_w_kernel(const float* __restrict__ W)
{
    const int nt = blockIdx.x >> 3;
    const int c  = blockIdx.x & 7;
    const int tid = threadIdx.x;
    const int row = tid >> 1;              // 0..127 (n within tile)
    const int kh  = (tid & 1) * 32;        // k element offset half-row

    const float* src = W + (size_t)(nt * NT + row) * H_DIM + c * KC + kh;
    char* dst = (char*)g_Wh + (size_t)(blockIdx.x) * 16384;

    const uint32_t rowoff = (uint32_t)row * 128;
    #pragma unroll
    for (int i = 0; i < 8; i++) {
        float4 xv = *(const float4*)(src + i * 4);
        uint2 hv;
        hv.x = pack_h2(xv.x, xv.y);
        hv.y = pack_h2(xv.z, xv.w);
        const uint32_t off = swz(rowoff, (uint32_t)(kh * 2 + i * 8));
        *(uint2*)(dst + off) = hv;
    }
}

// ---------------------------------------------------------------------------
// X pre-convert: fp32 [M,512] -> pre-swizzled fp16 tiles (t m-tile, c chunk)
// grid: (1024, 8) blocks, 256 threads. DRAM-bound (read 256MB, write 128MB).
// ---------------------------------------------------------------------------
__global__ void __launch_bounds__(256)
convert_x_kernel(const float* __restrict__ X)
{
    const int t = blockIdx.x;
    const int c = blockIdx.y;
    const int tid = threadIdx.x;
    const int row = tid >> 1;              // 0..127 (m within tile)
    const int kh  = (tid & 1) * 32;

    const float* src = X + (size_t)(t * MT + row) * H_DIM + c * KC + kh;
    char* dst = (char*)g_Xh + ((size_t)(t * NKCH + c)) * 16384;

    const uint32_t rowoff = (uint32_t)row * 128;
    #pragma unroll
    for (int i = 0; i < 8; i++) {
        float4 xv = *(const float4*)(src + i * 4);
        uint2 hv;
        hv.x = pack_h2(xv.x, xv.y);
        hv.y = pack_h2(xv.z, xv.w);
        const uint32_t off = swz(rowoff, (uint32_t)(kh * 2 + i * 8));
        *(uint2*)(dst + off) = hv;
    }
}

// ---------------------------------------------------------------------------
// Scores GEMM via mma.sync fp16 (single term, fp32 accum), fused tanh.v
// reduce. A and B both pre-converted fp16, pure cp.async mainloop.
// grid (4 n-tiles, 1024 m-tiles) nt-fast for X L2 reuse.
// 512 threads / 16 warps, 3-stage pipeline, 2 CTAs/SM.
// ---------------------------------------------------------------------------
__global__ void __launch_bounds__(512, 2)
scores_gemm_mma(const float* __restrict__ bias,
                const float* __restrict__ v)
{
    extern __shared__ char smem[];
    __shared__ float red[4][MT];

    const uint32_t sb = smem_u32(smem);
    const int tid  = threadIdx.x;
    const int wid  = tid >> 5;
    const int lane = tid & 31;
    const int wm   = wid & 3;      // warp m index (0..3)
    const int wn   = wid >> 2;     // warp n index (0..3)
    const int nt = blockIdx.x;     // n-tile (fast dim -> adjacent CTAs share X)
    const int t  = blockIdx.y;     // m-tile

    // A/B global tiles (pre-swizzled 16KB blobs)
    const char* ag = (const char*)g_Xh + (size_t)(t * NKCH) * 16384;
    const char* bg = (const char*)g_Wh + (size_t)(nt * NKCH) * 16384;

    // ldmatrix row bases; column = kb + ks*32 composed inside the swizzle
    const int lrow = lane & 15;
    const uint32_t kb = (lane >> 4) * 16;
    uint32_t a_rowb[2], b_rowb[2];
    #pragma unroll
    for (int mi = 0; mi < 2; mi++)
        a_rowb[mi] = (uint32_t)(wm * 32 + mi * 16 + lrow) * 128;
    #pragma unroll
    for (int np = 0; np < 2; np++)
        b_rowb[np] = (uint32_t)(wn * 32 + np * 16 + lrow) * 128;

    float acc[2][4][4];
    #pragma unroll
    for (int mi = 0; mi < 2; mi++)
        #pragma unroll
        for (int ni = 0; ni < 4; ni++)
            #pragma unroll
            for (int j = 0; j < 4; j++) acc[mi][ni][j] = 0.f;

    // cp.async A+B for chunk c into stage c%3 (one commit group per chunk)
    auto ab_load = [&](int c) {
        const uint32_t stb = sb + (uint32_t)(c % NSTAGE) * STAGE;
        const char* ah = ag + (size_t)c * 16384;
        const char* bh = bg + (size_t)c * 16384;
        #pragma unroll
        for (int it = 0; it < 2; it++) {
            cp_async16(stb + A_OFF + tid * 16 + it * 8192, ah + tid * 16 + it * 8192);
            cp_async16(stb + B_OFF + tid * 16 + it * 8192, bh + tid * 16 + it * 8192);
        }
        cp_async_commit();
    };

    // ---- prologue: chunks 0, 1 ----
    ab_load(0);
    ab_load(1);

    for (int c = 0; c < NKCH; c++) {
        if (c == NKCH - 1) asm volatile("cp.async.wait_group 0;" ::: "memory");
        else               asm volatile("cp.async.wait_group 1;" ::: "memory");
        __syncthreads();

        if (c + 2 < NKCH)
            ab_load(c + 2);     // async, overlaps compute below; stage free

        // ---- compute chunk c ----
        const uint32_t st = sb + (uint32_t)(c % NSTAGE) * STAGE;
        #pragma unroll
        for (int ks = 0; ks < KC / 16; ks++) {
            const uint32_t kcol = kb + ks * 32;   // < 128, composed into swizzle
            uint32_t ah[2][4], bh[2][4];
            #pragma unroll
            for (int mi = 0; mi < 2; mi++)
                ldsm_x4(ah[mi], st + A_OFF + swz(a_rowb[mi], kcol));
            #pragma unroll
            for (int np = 0; np < 2; np++)
                ldsm_x4(bh[np], st + B_OFF + swz(b_rowb[np], kcol));
            #pragma unroll
            for (int mi = 0; mi < 2; mi++)
                #pragma unroll
                for (int np = 0; np < 2; np++)
                    #pragma unroll
                    for (int hf = 0; hf < 2; hf++)
                        mma16816(acc[mi][np * 2 + hf], ah[mi],
                                 bh[np][hf], bh[np][hf + 2]);
        }
    }

    // ---- epilogue: rsum[row] = sum_n v[n]*tanh(acc + b[n]) ----
    const int ncol0 = nt * NT + wn * 32 + (lane & 3) * 2;
    float rs[2][2] = {{0.f, 0.f}, {0.f, 0.f}};
    #pragma unroll
    for (int np = 0; np < 2; np++) {
        #pragma unroll
        for (int hf = 0; hf < 2; hf++) {
            #pragma unroll
            for (int cc = 0; cc < 2; cc++) {
                const int col = ncol0 + np * 16 + hf * 8 + cc;
                const float bb = bias[col];
                const float vv = v[col];
                #pragma unroll
                for (int mi = 0; mi < 2; mi++) {
                    float x0 = acc[mi][np * 2 + hf][cc] + bb;       // row groupID
                    float x1 = acc[mi][np * 2 + hf][cc + 2] + bb;   // row groupID+8
                    float t0, t1;
                    asm("tanh.approx.f32 %0, %1;" : "=f"(t0) : "f"(x0));
                    asm("tanh.approx.f32 %0, %1;" : "=f"(t1) : "f"(x1));
                    rs[mi][0] = fmaf(t0, vv, rs[mi][0]);
                    rs[mi][1] = fmaf(t1, vv, rs[mi][1]);
                }
            }
        }
    }
    // reduce across the 4 lanes sharing a row (lane bits 0-1)
    #pragma unroll
    for (int mi = 0; mi < 2; mi++)
        #pragma unroll
        for (int h = 0; h < 2; h++) {
            rs[mi][h] += __shfl_xor_sync(0xffffffffu, rs[mi][h], 1);
            rs[mi][h] += __shfl_xor_sync(0xffffffffu, rs[mi][h], 2);
        }

    __syncthreads();   // all compute done before red[] use
    if ((lane & 3) == 0) {
        #pragma unroll
        for (int mi = 0; mi < 2; mi++)
            #pragma unroll
            for (int h = 0; h < 2; h++)
                red[wn][wm * 32 + mi * 16 + h * 8 + (lane >> 2)] = rs[mi][h];
    }
    __syncthreads();
    if (tid < MT) {
        float s = red[0][tid] + red[1][tid] + red[2][tid] + red[3][tid];
        g_score_part[(size_t)nt * M_DIM + (size_t)t * MT + tid] = s;
    }
}

// ---------------------------------------------------------------------------
// Softmax (folds 4 n-tile partials), mask as int32
// ---------------------------------------------------------------------------
__device__ __forceinline__ float warp_max(float v) {
    #pragma unroll
    for (int o = 16; o > 0; o >>= 1) v = fmaxf(v, __shfl_xor_sync(0xffffffffu, v, o));
    return v;
}
__device__ __forceinline__ float warp_sum(float v) {
    #pragma unroll
    for (int o = 16; o > 0; o >>= 1) v += __shfl_xor_sync(0xffffffffu, v, o);
    return v;
}

__global__ void __launch_bounds__(256)
softmax_kernel(const int* __restrict__ mask, float* __restrict__ weights)
{
    const int b    = blockIdx.x;
    const int tid  = threadIdx.x;
    const int lane = tid & 31;
    const int wid  = tid >> 5;

    __shared__ float red[8];

    float vals[8];
    float mx = -3.4e38f;
    #pragma unroll
    for (int i = 0; i < 8; i++) {
        const size_t m = (size_t)b * S_DIM + tid + i * 256;
        float sc = 0.f;
        #pragma unroll
        for (int n = 0; n < NTILES; n++)
            sc += g_score_part[(size_t)n * M_DIM + m];
        if (mask[m] == 0) sc = NEG_INF_SCORE;
        vals[i] = sc;
        mx = fmaxf(mx, sc);
    }

    mx = warp_max(mx);
    if (lane == 0) red[wid] = mx;
    __syncthreads();
    float bmax = red[0];
    #pragma unroll
    for (int i = 1; i < 8; i++) bmax = fmaxf(bmax, red[i]);
    __syncthreads();

    float s_sum = 0.f;
    #pragma unroll
    for (int i = 0; i < 8; i++) {
        vals[i] = __expf(vals[i] - bmax);
        s_sum += vals[i];
    }
    s_sum = warp_sum(s_sum);
    if (lane == 0) red[wid] = s_sum;
    __syncthreads();
    float total = red[0];
    #pragma unroll
    for (int i = 1; i < 8; i++) total += red[i];

    const float inv = 1.0f / total;
    #pragma unroll
    for (int i = 0; i < 8; i++)
        weights[(size_t)b * S_DIM + tid + i * 256] = vals[i] * inv;
}

// ---------------------------------------------------------------------------
// Context: weighted sum over S, reading the PRE-CONVERTED fp16 X tiles
// (halves DRAM traffic vs fp32 hidden). Block (sc, b), 128 threads:
// tid&63 -> 8 h-elements (one uint4 of halves), tid>>6 -> s parity.
// ---------------------------------------------------------------------------
__global__ void __launch_bounds__(128)
context_part_kernel(const float* __restrict__ weights)
{
    const int sc = blockIdx.x;          // 0..31
    const int b  = blockIdx.y;          // 0..63
    const int tid = threadIdx.x;
    const int th  = tid & 63;
    const int so  = tid >> 6;           // 0..1
    const int h8  = th * 8;             // h offset, step 8
    const int c   = h8 >> 6;            // k-chunk 0..7
    const uint32_t colb = (uint32_t)((h8 & 63) * 2);   // 0..112, 16B aligned

    const float* wrow = weights + (size_t)b * S_DIM + sc * S_PER_CHUNK;

    float acc[8];
    #pragma unroll
    for (int j = 0; j < 8; j++) acc[j] = 0.f;

    for (int i = so; i < S_PER_CHUNK; i += 2) {
        const int m   = b * S_DIM + sc * S_PER_CHUNK + i;
        const int t   = m >> 7;
        const int row = m & 127;
        const char* tile = (const char*)g_Xh + ((size_t)(t * NKCH + c)) * 16384;
        uint4 hv = *(const uint4*)(tile + swz((uint32_t)row * 128, colb));
        const float w = wrow[i];

        float2 f0 = __half22float2(*reinterpret_cast<__half2*>(&hv.x));
        float2 f1 = __half22float2(*reinterpret_cast<__half2*>(&hv.y));
        float2 f2 = __half22float2(*reinterpret_cast<__half2*>(&hv.z));
        float2 f3 = __half22float2(*reinterpret_cast<__half2*>(&hv.w));
        acc[0] = fmaf(w, f0.x, acc[0]); acc[1] = fmaf(w, f0.y, acc[1]);
        acc[2] = fmaf(w, f1.x, acc[2]); acc[3] = fmaf(w, f1.y, acc[3]);
        acc[4] = fmaf(w, f2.x, acc[4]); acc[5] = fmaf(w, f2.y, acc[5]);
        acc[6] = fmaf(w, f3.x, acc[6]); acc[7] = fmaf(w, f3.y, acc[7]);
    }

    float* dst = g_ctx_part + ((size_t)(sc * B_DIM + b)) * H_DIM + h8 + so * 4;
    // two threads (so=0,1) write disjoint float4 halves after cross-s merge
    // via shared: simpler -- each (so) holds partial over its s-parity; merge
    // through shuffle across the 64-thread boundary is not possible (different
    // warps), so use shared memory.
    __shared__ float part[2][64][8];
    #pragma unroll
    for (int j = 0; j < 8; j++) part[so][th][j] = acc[j];
    __syncthreads();
    if (so == 0) {
        float4 o0, o1;
        o0.x = acc[0] + part[1][th][0]; o0.y = acc[1] + part[1][th][1];
        o0.z = acc[2] + part[1][th][2]; o0.w = acc[3] + part[1][th][3];
        o1.x = acc[4] + part[1][th][4]; o1.y = acc[5] + part[1][th][5];
        o1.z = acc[6] + part[1][th][6]; o1.w = acc[7] + part[1][th][7];
        float* d = g_ctx_part + ((size_t)(sc * B_DIM + b)) * H_DIM + h8;
        *(float4*)(d)     = o0;
        *(float4*)(d + 4) = o1;
    }
    (void)dst;
}

__global__ void __launch_bounds__(256)
context_reduce_kernel(float* __restrict__ context)
{
    const int i = blockIdx.x * blockDim.x + threadIdx.x;
    float s = 0.f;
    #pragma unroll
    for (int n = 0; n < SCHUNK; n++)
        s += g_ctx_part[(size_t)n * (B_DIM * H_DIM) + i];
    context[i] = s;
}

// ---------------------------------------------------------------------------
extern "C" void kernel_launch(void* const* d_in, const int* in_sizes, int n_in,
                              void* d_out, int out_size)
{
    (void)in_sizes; (void)n_in; (void)out_size;
    const float* hidden = (const float*)d_in[0];
    const int*   mask   = (const int*)d_in[1];
    const float* W      = (const float*)d_in[2];
    const float* bias   = (const float*)d_in[3];
    const float* v      = (const float*)d_in[4];

    float* context = (float*)d_out;                          // [B, H]
    float* weights = (float*)d_out + (size_t)B_DIM * H_DIM;  // [B, S]

    cudaFuncSetAttribute(scores_gemm_mma,
                         cudaFuncAttributeMaxDynamicSharedMemorySize, GEMM_SMEM);

    convert_w_kernel<<<NTILES * NKCH, 256>>>(W);
    convert_x_kernel<<<dim3(NMTILES, NKCH), 256>>>(hidden);

    scores_gemm_mma<<<dim3(NTILES, NMTILES), 512, GEMM_SMEM>>>(bias, v);

    softmax_kernel<<<B_DIM, 256>>>(mask, weights);

    context_part_kernel<<<dim3(SCHUNK, B_DIM), 128>>>(weights);
    context_reduce_kernel<<<(B_DIM * H_DIM) / 256, 256>>>(context);
}